// round 13
// baseline (speedup 1.0000x reference)
#include <cuda_runtime.h>

#define NB      2
#define NPTS    8192
#define NDIM    64
#define KSEL    16
#define QB      32
#define CB      128
#define THREADS 128

// Precomputed squared norms (allocation-free scratch).
__device__ float g_sq[NB * NPTS];

// lexicographic (distance, index) ascending — stable top_k tie order
__device__ __forceinline__ bool keyless(float d1, int i1, float d2, int i2) {
    return (d1 < d2) || (d1 == d2 && i1 < i2);
}

// Serial insert into a shared sorted-16 list (lane 0 only). Re-checks the
// LIVE 16th entry, so stale screening thresholds are safe.
__device__ __forceinline__ void sins16(float* tl_d, int* tl_i, float dv, int idx) {
    if (keyless(dv, idx, tl_d[KSEL - 1], tl_i[KSEL - 1])) {
        int p = KSEL - 1;
        while (p > 0 && keyless(dv, idx, tl_d[p - 1], tl_i[p - 1])) {
            tl_d[p] = tl_d[p - 1];
            tl_i[p] = tl_i[p - 1];
            p--;
        }
        tl_d[p] = dv;
        tl_i[p] = idx;
    }
}

// ---------------------------------------------------------------------------
// Kernel 1: ||x||^2 per point — SAME sequential fma chain (c=0..63) as the
// dot products below, so the self-distance cancels to exactly 0 in fp32.
// ---------------------------------------------------------------------------
__global__ void norms_kernel(const float* __restrict__ x) {
    int p = blockIdx.x * blockDim.x + threadIdx.x;
    if (p >= NB * NPTS) return;
    int b = p >> 13;
    int n = p & (NPTS - 1);
    const float* xb = x + b * (NDIM * NPTS);
    float acc = 0.0f;
#pragma unroll
    for (int c = 0; c < NDIM; c++) {
        float v = xb[c * NPTS + n];
        acc = fmaf(v, v, acc);
    }
    g_sq[p] = acc;
}

// ---------------------------------------------------------------------------
// Kernel 2: fused Gram + warp-cooperative top-16.
//   128 threads. Thread (qg = tid>>4 in 0..7, cg = tid&15):
//   queries 4qg..4qg+3  x  candidates {4cg..4cg+3, 64+4cg..+3}.
//   Per k: 3 LDS.128 feed 32 FFMA (2x the FFMA-per-smem-byte of the old
//   2q x 8c tile — the crossbar was co-binding). Warp w owns queries
//   8w..8w+7; one sorted top-16 per query in smem, screened inserts.
// ---------------------------------------------------------------------------
__global__ __launch_bounds__(THREADS, 4) void knn_kernel(const float* __restrict__ x,
                                                         float* __restrict__ out) {
    __shared__ __align__(16) float qs[NDIM * QB];   //  8 KB  [k][q]
    __shared__ __align__(16) float cs[NDIM * CB];   // 32 KB  [k][p]
    __shared__ float cssq[CB];
    __shared__ float qsq[QB];
    __shared__ float tld[QB * KSEL];
    __shared__ int   tli[QB * KSEL];

    const int tid    = threadIdx.x;
    const int b      = blockIdx.y;
    const int n_base = blockIdx.x * QB;
    const float* xb  = x + b * (NDIM * NPTS);
    const float* sqb = g_sq + b * NPTS;

    for (int i = tid; i < NDIM * QB; i += THREADS) {
        int q = i & (QB - 1);
        int k = i >> 5;
        qs[k * QB + q] = xb[k * NPTS + n_base + q];
    }
    if (tid < QB) qsq[tid] = sqb[n_base + tid];
    for (int i = tid; i < QB * KSEL; i += THREADS) {
        tld[i] = __int_as_float(0x7f800000);   // +inf
        tli[i] = 0x7fffffff;
    }
    __syncthreads();

    const int lane = tid & 31;
    const int warp = tid >> 5;          // 0..3
    const int qg   = tid >> 4;          // 0..7  (4 queries each)
    const int cg   = tid & 15;          // 0..15 (8 candidates each)

    float sq[4];
#pragma unroll
    for (int s = 0; s < 4; s++) sq[s] = qsq[4 * qg + s];

    const float4* qs4 = reinterpret_cast<const float4*>(qs);   // [k*8 + qg]
    const float4* csr = reinterpret_cast<const float4*>(cs);   // [k*32 + ...]
    float4*       csw = reinterpret_cast<float4*>(cs);
    const float4* x4  = reinterpret_cast<const float4*>(xb);

    for (int base = 0; base < NPTS; base += CB) {
        __syncthreads();   // previous tile fully consumed

        for (int i = tid; i < NDIM * (CB / 4); i += THREADS) {
            int p4 = i & 31;
            int c  = i >> 5;
            csw[c * (CB / 4) + p4] = x4[(c * NPTS + base) / 4 + p4];
        }
        cssq[tid] = sqb[base + tid];           // tid covers 0..127 == CB
        __syncthreads();

        // --- Gram micro-tile: 4 queries x 8 candidates ---
        float acc[4][8];
#pragma unroll
        for (int s = 0; s < 4; s++)
#pragma unroll
            for (int j = 0; j < 8; j++) acc[s][j] = 0.0f;

#pragma unroll 8
        for (int k = 0; k < NDIM; k++) {
            float4 a  = qs4[k * (QB / 4) + qg];          // 4 queries
            float4 mA = csr[k * (CB / 4) + cg];          // cands 4cg..4cg+3
            float4 mB = csr[k * (CB / 4) + 16 + cg];     // cands 64+4cg..+3
            const float av[4] = {a.x, a.y, a.z, a.w};
#pragma unroll
            for (int s = 0; s < 4; s++) {
                acc[s][0] = fmaf(av[s], mA.x, acc[s][0]);
                acc[s][1] = fmaf(av[s], mA.y, acc[s][1]);
                acc[s][2] = fmaf(av[s], mA.z, acc[s][2]);
                acc[s][3] = fmaf(av[s], mA.w, acc[s][3]);
                acc[s][4] = fmaf(av[s], mB.x, acc[s][4]);
                acc[s][5] = fmaf(av[s], mB.y, acc[s][5]);
                acc[s][6] = fmaf(av[s], mB.z, acc[s][6]);
                acc[s][7] = fmaf(av[s], mB.w, acc[s][7]);
            }
        }

        // Distance epilogue in place (same expression/order as before).
#pragma unroll
        for (int j = 0; j < 8; j++) {
            int c = (j < 4) ? (4 * cg + j) : (64 + 4 * cg + (j - 4));
            float sc = cssq[c];
#pragma unroll
            for (int s = 0; s < 4; s++)
                acc[s][j] = (sq[s] + (-2.0f * acc[s][j])) + sc;
        }

        // --- Selection. Warp w owns queries 8w..8w+7:
        //   sub s: lanes 0-15 -> q = 8w+s, lanes 16-31 -> q = 8w+4+s.
#pragma unroll
        for (int sub = 0; sub < 4; sub++) {
            const int q_lo = 8 * warp + sub;
            const int q_hi = q_lo + 4;
            const int myq  = q_lo + ((lane >> 4) << 2);

            float thr  = tld[myq * KSEL + KSEL - 1];
            int   thri = tli[myq * KSEL + KSEL - 1];

            bool any = false;
#pragma unroll
            for (int j = 0; j < 8; j++) {
                int c = (j < 4) ? (4 * cg + j) : (64 + 4 * cg + (j - 4));
                any |= keyless(acc[sub][j], base + c, thr, thri);
            }

            unsigned scr = __ballot_sync(0xffffffffu, any);
            if (scr != 0u) {
#pragma unroll
                for (int j = 0; j < 8; j++) {
                    float d   = acc[sub][j];
                    int   cme = (j < 4) ? (4 * cg + j) : (64 + 4 * cg + (j - 4));
                    float lt  = tld[myq * KSEL + KSEL - 1];
                    int   lti = tli[myq * KSEL + KSEL - 1];
                    bool pass = keyless(d, base + cme, lt, lti);
                    unsigned bal = __ballot_sync(0xffffffffu, pass);
                    if (bal) {
                        unsigned lom = bal & 0xffffu;
                        while (lom) {
                            int src = __ffs(lom) - 1;
                            lom &= lom - 1;
                            float dv = __shfl_sync(0xffffffffu, d, src);
                            if (lane == 0) {
                                int c = (j < 4) ? (4 * src + j) : (64 + 4 * src + (j - 4));
                                sins16(tld + q_lo * KSEL, tli + q_lo * KSEL, dv, base + c);
                            }
                        }
                        unsigned him = bal >> 16;
                        while (him) {
                            int s = __ffs(him) - 1;
                            him &= him - 1;
                            float dv = __shfl_sync(0xffffffffu, d, s + 16);
                            if (lane == 0) {
                                int c = (j < 4) ? (4 * s + j) : (64 + 4 * s + (j - 4));
                                sins16(tld + q_hi * KSEL, tli + q_hi * KSEL, dv, base + c);
                            }
                        }
                        __syncwarp();
                    }
                }
            }
        }
    }

    // Output (2, NB, NPTS, KSEL), float32 values.
    __syncthreads();
    for (int i = tid; i < QB * KSEL; i += THREADS) {
        int q = i >> 4;
        int k = i & (KSEL - 1);
        int n = n_base + q;
        int base0 = (b * NPTS + n) * KSEL + k;            // plane 0: nn_idx
        int base1 = NB * NPTS * KSEL + base0;             // plane 1: center_idx
        out[base0] = (float)tli[q * KSEL + k];
        out[base1] = (float)n;
    }
}

extern "C" void kernel_launch(void* const* d_in, const int* in_sizes, int n_in,
                              void* d_out, int out_size) {
    const float* x = (const float*)d_in[0];
    float* out = (float*)d_out;
    norms_kernel<<<(NB * NPTS + 255) / 256, 256>>>(x);
    knn_kernel<<<dim3(NPTS / QB, NB), THREADS>>>(x, out);
}

// round 14
// speedup vs baseline: 1.5759x; 1.5759x over previous
#include <cuda_runtime.h>

#define NB      2
#define NPTS    8192
#define NDIM    64
#define KSEL    16
#define QB      32
#define CB      128
#define THREADS 256

// Precomputed squared norms (allocation-free scratch).
__device__ float g_sq[NB * NPTS];

// lexicographic (distance, index) ascending — stable top_k tie order
__device__ __forceinline__ bool keyless(float d1, int i1, float d2, int i2) {
    return (d1 < d2) || (d1 == d2 && i1 < i2);
}

// Serial insert into a shared sorted-16 list (lane 0 only). Re-checks the
// LIVE 16th entry, so stale screening thresholds are safe.
__device__ __forceinline__ void sins16(float* tl_d, int* tl_i, float dv, int idx) {
    if (keyless(dv, idx, tl_d[KSEL - 1], tl_i[KSEL - 1])) {
        int p = KSEL - 1;
        while (p > 0 && keyless(dv, idx, tl_d[p - 1], tl_i[p - 1])) {
            tl_d[p] = tl_d[p - 1];
            tl_i[p] = tl_i[p - 1];
            p--;
        }
        tl_d[p] = dv;
        tl_i[p] = idx;
    }
}

// ---------------------------------------------------------------------------
// Kernel 1: ||x||^2 per point — SAME sequential fma chain (c=0..63) as the
// dot products below, so the self-distance cancels to exactly 0 in fp32.
// ---------------------------------------------------------------------------
__global__ void norms_kernel(const float* __restrict__ x) {
    int p = blockIdx.x * blockDim.x + threadIdx.x;
    if (p >= NB * NPTS) return;
    int b = p >> 13;
    int n = p & (NPTS - 1);
    const float* xb = x + b * (NDIM * NPTS);
    float acc = 0.0f;
#pragma unroll
    for (int c = 0; c < NDIM; c++) {
        float v = xb[c * NPTS + n];
        acc = fmaf(v, v, acc);
    }
    g_sq[p] = acc;
}

// ---------------------------------------------------------------------------
// Kernel 2: fused Gram + warp-cooperative top-16 — round-11 structure with an
// explicitly software-pipelined, fully-unrolled k-loop and named scalar
// accumulators (the 29-cyc-per-instruction issue pattern of rounds 10-13
// indicts just-in-time LDS consumption in the partially-unrolled loop).
// ---------------------------------------------------------------------------
__global__ __launch_bounds__(THREADS) void knn_kernel(const float* __restrict__ x,
                                                      float* __restrict__ out) {
    __shared__ __align__(16) float qs[NDIM * QB];   //  8 KB  [k][q]
    __shared__ __align__(16) float cs[NDIM * CB];   // 32 KB  [k][p]
    __shared__ float cssq[CB];
    __shared__ float qsq[QB];
    __shared__ float tld[QB * KSEL];
    __shared__ int   tli[QB * KSEL];

    const int tid    = threadIdx.x;
    const int b      = blockIdx.y;
    const int n_base = blockIdx.x * QB;
    const float* xb  = x + b * (NDIM * NPTS);
    const float* sqb = g_sq + b * NPTS;

    for (int i = tid; i < NDIM * QB; i += THREADS) {
        int q = i & (QB - 1);
        int k = i >> 5;
        qs[k * QB + q] = xb[k * NPTS + n_base + q];
    }
    if (tid < QB) qsq[tid] = sqb[n_base + tid];
    for (int i = tid; i < QB * KSEL; i += THREADS) {
        tld[i] = __int_as_float(0x7f800000);   // +inf
        tli[i] = 0x7fffffff;
    }
    __syncthreads();

    const int lane = tid & 31;
    const int warp = tid >> 5;
    const int qg   = tid >> 4;          // 0..15
    const int cg   = tid & 15;          // 0..15
    const float sq0 = qsq[2 * qg];
    const float sq1 = qsq[2 * qg + 1];

    const int myq0 = 4 * warp + 0 + ((lane >> 4) << 1);
    const int myq1 = 4 * warp + 1 + ((lane >> 4) << 1);

    const float2* qs2 = reinterpret_cast<const float2*>(qs);   // [k*16 + qg]
    const float4* csr = reinterpret_cast<const float4*>(cs);   // [k*32 + ...]
    float4*       csw = reinterpret_cast<float4*>(cs);
    const float4* x4  = reinterpret_cast<const float4*>(xb);

    for (int base = 0; base < NPTS; base += CB) {
        __syncthreads();   // previous tile fully consumed

        for (int i = tid; i < NDIM * (CB / 4); i += THREADS) {
            int p4 = i & 31;
            int c  = i >> 5;
            csw[c * (CB / 4) + p4] = x4[(c * NPTS + base) / 4 + p4];
        }
        if (tid < CB) cssq[tid] = sqb[base + tid];
        __syncthreads();

        // --- Gram micro-tile: 2 queries x 8 candidates, named scalars,
        //     fully unrolled k with 1-deep explicit load pipeline. ---
        float a00 = 0.f, a01 = 0.f, a02 = 0.f, a03 = 0.f;
        float a04 = 0.f, a05 = 0.f, a06 = 0.f, a07 = 0.f;
        float a10 = 0.f, a11 = 0.f, a12 = 0.f, a13 = 0.f;
        float a14 = 0.f, a15 = 0.f, a16 = 0.f, a17 = 0.f;

        float2 aC = qs2[qg];                       // k = 0
        float4 mAC = csr[cg];
        float4 mBC = csr[16 + cg];

#pragma unroll
        for (int k = 0; k < NDIM; k++) {
            float2 aN; float4 mAN, mBN;
            if (k + 1 < NDIM) {                    // prefetch k+1 BEFORE using k
                aN  = qs2[(k + 1) * (QB / 2) + qg];
                mAN = csr[(k + 1) * (CB / 4) + cg];
                mBN = csr[(k + 1) * (CB / 4) + 16 + cg];
            }
            a00 = fmaf(aC.x, mAC.x, a00);
            a01 = fmaf(aC.x, mAC.y, a01);
            a02 = fmaf(aC.x, mAC.z, a02);
            a03 = fmaf(aC.x, mAC.w, a03);
            a04 = fmaf(aC.x, mBC.x, a04);
            a05 = fmaf(aC.x, mBC.y, a05);
            a06 = fmaf(aC.x, mBC.z, a06);
            a07 = fmaf(aC.x, mBC.w, a07);
            a10 = fmaf(aC.y, mAC.x, a10);
            a11 = fmaf(aC.y, mAC.y, a11);
            a12 = fmaf(aC.y, mAC.z, a12);
            a13 = fmaf(aC.y, mAC.w, a13);
            a14 = fmaf(aC.y, mBC.x, a14);
            a15 = fmaf(aC.y, mBC.y, a15);
            a16 = fmaf(aC.y, mBC.z, a16);
            a17 = fmaf(aC.y, mBC.w, a17);
            if (k + 1 < NDIM) { aC = aN; mAC = mAN; mBC = mBN; }
        }

        // Distance epilogue (same expression/order as all passing rounds).
        float d0[8], d1[8];
        d0[0] = (sq0 + (-2.0f * a00));  d0[1] = (sq0 + (-2.0f * a01));
        d0[2] = (sq0 + (-2.0f * a02));  d0[3] = (sq0 + (-2.0f * a03));
        d0[4] = (sq0 + (-2.0f * a04));  d0[5] = (sq0 + (-2.0f * a05));
        d0[6] = (sq0 + (-2.0f * a06));  d0[7] = (sq0 + (-2.0f * a07));
        d1[0] = (sq1 + (-2.0f * a10));  d1[1] = (sq1 + (-2.0f * a11));
        d1[2] = (sq1 + (-2.0f * a12));  d1[3] = (sq1 + (-2.0f * a13));
        d1[4] = (sq1 + (-2.0f * a14));  d1[5] = (sq1 + (-2.0f * a15));
        d1[6] = (sq1 + (-2.0f * a16));  d1[7] = (sq1 + (-2.0f * a17));
#pragma unroll
        for (int j = 0; j < 8; j++) {
            int c = (j < 4) ? (4 * cg + j) : (64 + 4 * cg + (j - 4));
            float sc = cssq[c];
            d0[j] = d0[j] + sc;
            d1[j] = d1[j] + sc;
        }

        // --- Selection: one-shot screen per sub, slow path only if needed ---
#pragma unroll
        for (int sub = 0; sub < 2; sub++) {
            const int q_lo = 4 * warp + sub;
            const int q_hi = q_lo + 2;
            const int myq  = (sub == 0) ? myq0 : myq1;

            float thr  = tld[myq * KSEL + KSEL - 1];
            int   thri = tli[myq * KSEL + KSEL - 1];

            bool any = false;
#pragma unroll
            for (int j = 0; j < 8; j++) {
                float d = (sub == 0) ? d0[j] : d1[j];
                int   c = (j < 4) ? (4 * cg + j) : (64 + 4 * cg + (j - 4));
                any |= keyless(d, base + c, thr, thri);
            }

            unsigned scr = __ballot_sync(0xffffffffu, any);
            if (scr != 0u) {
#pragma unroll
                for (int j = 0; j < 8; j++) {
                    float d   = (sub == 0) ? d0[j] : d1[j];
                    int   cme = (j < 4) ? (4 * cg + j) : (64 + 4 * cg + (j - 4));
                    float lt  = tld[myq * KSEL + KSEL - 1];
                    int   lti = tli[myq * KSEL + KSEL - 1];
                    bool pass = keyless(d, base + cme, lt, lti);
                    unsigned bal = __ballot_sync(0xffffffffu, pass);
                    if (bal) {
                        unsigned lom = bal & 0xffffu;
                        while (lom) {
                            int src = __ffs(lom) - 1;
                            lom &= lom - 1;
                            float dv = __shfl_sync(0xffffffffu, d, src);
                            if (lane == 0) {
                                int c = (j < 4) ? (4 * src + j) : (64 + 4 * src + (j - 4));
                                sins16(tld + q_lo * KSEL, tli + q_lo * KSEL, dv, base + c);
                            }
                        }
                        unsigned him = bal >> 16;
                        while (him) {
                            int s = __ffs(him) - 1;
                            him &= him - 1;
                            float dv = __shfl_sync(0xffffffffu, d, s + 16);
                            if (lane == 0) {
                                int c = (j < 4) ? (4 * s + j) : (64 + 4 * s + (j - 4));
                                sins16(tld + q_hi * KSEL, tli + q_hi * KSEL, dv, base + c);
                            }
                        }
                        __syncwarp();
                    }
                }
            }
        }
    }

    // Output (2, NB, NPTS, KSEL), float32 values.
    __syncthreads();
    for (int i = tid; i < QB * KSEL; i += THREADS) {
        int q = i >> 4;
        int k = i & (KSEL - 1);
        int n = n_base + q;
        int base0 = (b * NPTS + n) * KSEL + k;            // plane 0: nn_idx
        int base1 = NB * NPTS * KSEL + base0;             // plane 1: center_idx
        out[base0] = (float)tli[q * KSEL + k];
        out[base1] = (float)n;
    }
}

extern "C" void kernel_launch(void* const* d_in, const int* in_sizes, int n_in,
                              void* d_out, int out_size) {
    const float* x = (const float*)d_in[0];
    float* out = (float*)d_out;
    norms_kernel<<<(NB * NPTS + 255) / 256, 256>>>(x);
    knn_kernel<<<dim3(NPTS / QB, NB), THREADS>>>(x, out);
}